// round 10
// baseline (speedup 1.0000x reference)
#include <cuda_runtime.h>
#include <cstdint>

// TemporalPyramidPooling: overlapping masked window means at w=4/8/16, stride w/2.
// Hierarchical non-overlapping pair sums; float4-vectorized over D.
// R10: 4-warp CTAs splitting T (4 groups/warp, 16-group tile); intra-CTA boundary
//      windows stitched via shared memory (1 sync) -> halo loads drop 25% -> 6.25%.
//      DSPLIT=4 on D (lanes cover 32 float4 columns). evict_last x loads, __stcs stores.
//
//   x    [B=8, T=4096, D=512] f32
//   mask [B, T]  (bool; stored as 1-byte or int32 0/1 -- detected at runtime)
// Outputs concatenated f32:
//   vis4 [B,2047,D], vis8 [B,1023,D], vis16 [B,511,D],
//   msk4 [B,2047],   msk8 [B,1023],   msk16 [B,511]

namespace {
constexpr int B   = 8;
constexpr int T   = 4096;
constexpr int D   = 512;
constexpr int D4  = D / 4;                   // 128 float4 lanes
constexpr int S4  = 2047;
constexpr int S8  = 1023;
constexpr int S16 = 511;
constexpr int NGROUPS = T / 8;               // 512 pair8 groups per batch
constexpr int GPW  = 4;                      // groups per warp
constexpr int NWARP = 4;                     // warps per CTA (split T)
constexpr int GPCTA = GPW * NWARP;           // 16 groups per CTA tile
constexpr int TILES_PER_B = NGROUPS / GPCTA; // 32
constexpr int DSPLIT = 4;                    // CTAs along D
constexpr int LANES = D4 / DSPLIT;           // 32 lanes
}

// 1/max(count,1e-6) for counts 0..16 (count==0 -> sum==0, product 0 matches ref)
__constant__ float c_inv[17] = {
    1e6f, 1.0f, 0.5f, 1.0f/3.0f, 0.25f, 0.2f, 1.0f/6.0f, 1.0f/7.0f,
    0.125f, 1.0f/9.0f, 0.1f, 1.0f/11.0f, 1.0f/12.0f, 1.0f/13.0f,
    1.0f/14.0f, 1.0f/15.0f, 0.0625f
};

__device__ __forceinline__ float4 f4add(float4 a, float4 b) {
    return make_float4(a.x + b.x, a.y + b.y, a.z + b.z, a.w + b.w);
}
__device__ __forceinline__ float4 f4scale(float4 a, float s) {
    return make_float4(a.x * s, a.y * s, a.z * s, a.w * s);
}
__device__ __forceinline__ float4 f4zero() { return make_float4(0.f, 0.f, 0.f, 0.f); }

__device__ __forceinline__ uint64_t make_evict_last_policy() {
    uint64_t pol;
    asm("createpolicy.fractional.L2::evict_last.b64 %0, 1.0;" : "=l"(pol));
    return pol;
}
__device__ __forceinline__ float4 ldg_el(const float4* p, uint64_t pol) {
    float4 r;
    asm("ld.global.nc.L2::cache_hint.v4.f32 {%0,%1,%2,%3}, [%4], %5;"
        : "=f"(r.x), "=f"(r.y), "=f"(r.z), "=f"(r.w) : "l"(p), "l"(pol));
    return r;
}

struct GroupSums {
    float4 c0, c1, c2, c3;   // pair2 sums
    float4 d0, d1;           // pair4 sums
    float4 e;                // pair8 sum
    int n0, n1, n2, n3, m0, m1, q;
};

__device__ __forceinline__ GroupSums load_group(
    const float4* __restrict__ xb, const void* __restrict__ mask_raw,
    bool mask_is_byte, int b, int g, uint64_t pol)
{
    const int t0 = g * 8;
    int mi[8];
    if (mask_is_byte) {
        const uint8_t* mb = (const uint8_t*)mask_raw + (size_t)b * T + t0;
        const uint64_t mw = *reinterpret_cast<const uint64_t*>(mb);
        #pragma unroll
        for (int i = 0; i < 8; ++i) mi[i] = (int)((mw >> (8 * i)) & 1u);
    } else {
        const int4* mw = reinterpret_cast<const int4*>(
            (const int*)mask_raw + (size_t)b * T + t0);
        int4 a = mw[0], c = mw[1];
        mi[0] = (a.x != 0); mi[1] = (a.y != 0); mi[2] = (a.z != 0); mi[3] = (a.w != 0);
        mi[4] = (c.x != 0); mi[5] = (c.y != 0); mi[6] = (c.z != 0); mi[7] = (c.w != 0);
    }

    float4 v[8];
    const float4* xp = xb + (size_t)t0 * D4;
    #pragma unroll
    for (int i = 0; i < 8; ++i) v[i] = ldg_el(xp + (size_t)i * D4, pol);
    #pragma unroll
    for (int i = 0; i < 8; ++i) if (!mi[i]) v[i] = f4zero();

    GroupSums s;
    s.c0 = f4add(v[0], v[1]); s.c1 = f4add(v[2], v[3]);
    s.c2 = f4add(v[4], v[5]); s.c3 = f4add(v[6], v[7]);
    s.n0 = mi[0] + mi[1]; s.n1 = mi[2] + mi[3];
    s.n2 = mi[4] + mi[5]; s.n3 = mi[6] + mi[7];
    s.d0 = f4add(s.c0, s.c1); s.d1 = f4add(s.c2, s.c3);
    s.m0 = s.n0 + s.n1; s.m1 = s.n2 + s.n3;
    s.e  = f4add(s.d0, s.d1);
    s.q  = s.m0 + s.m1;
    return s;
}

__global__ void __launch_bounds__(NWARP * 32, 7)
tpp_kernel(const float4* __restrict__ x,
           const void* __restrict__ mask_raw,
           float* __restrict__ out)
{
    const int lane  = threadIdx.x & 31;
    const int w     = threadIdx.x >> 5;          // warp id 0..3 (splits T)
    const int blk   = blockIdx.x;                // 0..1023
    const int dpart = blk % DSPLIT;
    const int tile  = blk / DSPLIT;              // 0..255
    const int b     = tile / TILES_PER_B;
    const int g0cta = (tile % TILES_PER_B) * GPCTA;
    const int g0    = g0cta + w * GPW;           // this warp's first group
    const int d4    = dpart * LANES + lane;      // 0..127

    const uint64_t pol = make_evict_last_policy();

    // ---- mask storage-layout detection (byte vs int32), warp-uniform ----
    unsigned mv = ((const unsigned*)mask_raw)[lane];
    const bool mask_is_byte = __any_sync(0xffffffffu, mv > 1u);

    const float4* xb = x + (size_t)b * T * D4 + d4;

    float4* const vis4  = (float4*)out;
    float4* const vis8  = vis4  + (size_t)B * S4  * D4;
    float4* const vis16 = vis8  + (size_t)B * S8  * D4;
    float*  const msk4  = out + (size_t)B * (S4 + S8 + S16) * D;
    float*  const msk8  = msk4 + B * S4;
    float*  const msk16 = msk8 + B * S8;

    const bool writeMsk = (lane == 0) && (dpart == 0);

    // smem for warp-boundary partials
    __shared__ float4 s_c3[NWARP][LANES];
    __shared__ float4 s_d1[NWARP][LANES];
    __shared__ float4 s_e [NWARP][LANES];
    __shared__ int    s_cnt[NWARP];              // n3 | m1<<8 | q<<16

    // retained first-group sums (for left-boundary stitch)
    float4 f_c0, f_d0, f_e;
    int    f_n0, f_m0, f_q;

    float4 prev_c3 = f4zero(), prev_d1 = f4zero(), prev_e = f4zero();
    int    prev_n3 = 0,        prev_m1 = 0,        prev_q = 0;

    #pragma unroll
    for (int k = 0; k < GPW; ++k) {
        const int g = g0 + k;
        const GroupSums s = load_group(xb, mask_raw, mask_is_byte, b, g, pol);

        if (k == 0) {
            f_c0 = s.c0; f_d0 = s.d0; f_e = s.e;
            f_n0 = s.n0; f_m0 = s.m0; f_q = s.q;
        } else {
            {   // win4 at 4g-1 (crosses group boundary, in-register prev)
                const int si = 4 * g - 1;
                const int cnt = prev_n3 + s.n0;
                __stcs(&vis4[(size_t)(b * S4 + si) * D4 + d4],
                       f4scale(f4add(prev_c3, s.c0), c_inv[cnt]));
                if (writeMsk) __stcs(&msk4[b * S4 + si], (cnt > 0) ? 1.0f : 0.0f);
            }
            {   // win8 at 2g-1
                const int h = 2 * g - 1;
                const int cnt = prev_m1 + s.m0;
                __stcs(&vis8[(size_t)(b * S8 + h) * D4 + d4],
                       f4scale(f4add(prev_d1, s.d0), c_inv[cnt]));
                if (writeMsk) __stcs(&msk8[b * S8 + h], (cnt > 0) ? 1.0f : 0.0f);
            }
            {   // win16 at g-1
                const int cnt = prev_q + s.q;
                __stcs(&vis16[(size_t)(b * S16 + (g - 1)) * D4 + d4],
                       f4scale(f4add(prev_e, s.e), c_inv[cnt]));
                if (writeMsk) __stcs(&msk16[b * S16 + (g - 1)], (cnt > 0) ? 1.0f : 0.0f);
            }
        }
        {   // in-tile outputs
            const int si = 4 * g;
            int cnt;
            cnt = s.n0 + s.n1;
            __stcs(&vis4[(size_t)(b * S4 + si    ) * D4 + d4],
                   f4scale(f4add(s.c0, s.c1), c_inv[cnt]));
            if (writeMsk) __stcs(&msk4[b * S4 + si    ], (cnt > 0) ? 1.0f : 0.0f);
            cnt = s.n1 + s.n2;
            __stcs(&vis4[(size_t)(b * S4 + si + 1) * D4 + d4],
                   f4scale(f4add(s.c1, s.c2), c_inv[cnt]));
            if (writeMsk) __stcs(&msk4[b * S4 + si + 1], (cnt > 0) ? 1.0f : 0.0f);
            cnt = s.n2 + s.n3;
            __stcs(&vis4[(size_t)(b * S4 + si + 2) * D4 + d4],
                   f4scale(f4add(s.c2, s.c3), c_inv[cnt]));
            if (writeMsk) __stcs(&msk4[b * S4 + si + 2], (cnt > 0) ? 1.0f : 0.0f);

            const int h = 2 * g;
            cnt = s.m0 + s.m1;
            __stcs(&vis8[(size_t)(b * S8 + h) * D4 + d4],
                   f4scale(f4add(s.d0, s.d1), c_inv[cnt]));
            if (writeMsk) __stcs(&msk8[b * S8 + h], (cnt > 0) ? 1.0f : 0.0f);
        }

        prev_c3 = s.c3; prev_d1 = s.d1; prev_e = s.e;
        prev_n3 = s.n3; prev_m1 = s.m1; prev_q = s.q;
    }

    // ---- publish last-group partials for the next warp ----
    s_c3[w][lane] = prev_c3;
    s_d1[w][lane] = prev_d1;
    s_e [w][lane] = prev_e;
    if (lane == 0) s_cnt[w] = prev_n3 | (prev_m1 << 8) | (prev_q << 16);
    __syncthreads();

    // ---- intra-CTA boundary: warp w>0 stitches with warp w-1's partials ----
    if (w > 0) {
        const float4 p_c3 = s_c3[w - 1][lane];
        const float4 p_d1 = s_d1[w - 1][lane];
        const float4 p_e  = s_e [w - 1][lane];
        const int pc = s_cnt[w - 1];
        const int p_n3 = pc & 0xff, p_m1 = (pc >> 8) & 0xff, p_q = (pc >> 16) & 0xff;

        const int g = g0;  // this warp's first group
        {   // win4 at 4g-1
            const int si = 4 * g - 1;
            const int cnt = p_n3 + f_n0;
            __stcs(&vis4[(size_t)(b * S4 + si) * D4 + d4],
                   f4scale(f4add(p_c3, f_c0), c_inv[cnt]));
            if (writeMsk) __stcs(&msk4[b * S4 + si], (cnt > 0) ? 1.0f : 0.0f);
        }
        {   // win8 at 2g-1
            const int h = 2 * g - 1;
            const int cnt = p_m1 + f_m0;
            __stcs(&vis8[(size_t)(b * S8 + h) * D4 + d4],
                   f4scale(f4add(p_d1, f_d0), c_inv[cnt]));
            if (writeMsk) __stcs(&msk8[b * S8 + h], (cnt > 0) ? 1.0f : 0.0f);
        }
        {   // win16 at g-1
            const int cnt = p_q + f_q;
            __stcs(&vis16[(size_t)(b * S16 + (g - 1)) * D4 + d4],
                   f4scale(f4add(p_e, f_e), c_inv[cnt]));
            if (writeMsk) __stcs(&msk16[b * S16 + (g - 1)], (cnt > 0) ? 1.0f : 0.0f);
        }
    }

    // ---- CTA-level halo: warp 3 stitches into the next tile's first group ----
    if (w == NWARP - 1) {
        const int gH = g0cta + GPCTA;
        if (gH < NGROUPS) {
            const GroupSums s = load_group(xb, mask_raw, mask_is_byte, b, gH, pol);
            {   // win4 at 4*gH-1
                const int si = 4 * gH - 1;
                const int cnt = prev_n3 + s.n0;
                __stcs(&vis4[(size_t)(b * S4 + si) * D4 + d4],
                       f4scale(f4add(prev_c3, s.c0), c_inv[cnt]));
                if (writeMsk) __stcs(&msk4[b * S4 + si], (cnt > 0) ? 1.0f : 0.0f);
            }
            {   // win8 at 2*gH-1
                const int h = 2 * gH - 1;
                const int cnt = prev_m1 + s.m0;
                __stcs(&vis8[(size_t)(b * S8 + h) * D4 + d4],
                       f4scale(f4add(prev_d1, s.d0), c_inv[cnt]));
                if (writeMsk) __stcs(&msk8[b * S8 + h], (cnt > 0) ? 1.0f : 0.0f);
            }
            {   // win16 at gH-1
                const int cnt = prev_q + s.q;
                __stcs(&vis16[(size_t)(b * S16 + (gH - 1)) * D4 + d4],
                       f4scale(f4add(prev_e, s.e), c_inv[cnt]));
                if (writeMsk) __stcs(&msk16[b * S16 + (gH - 1)], (cnt > 0) ? 1.0f : 0.0f);
            }
        }
    }
}

extern "C" void kernel_launch(void* const* d_in, const int* in_sizes, int n_in,
                              void* d_out, int out_size)
{
    const float4* x    = (const float4*)d_in[0];
    const void*   mask = (const void*)d_in[1];
    float*        out  = (float*)d_out;

    tpp_kernel<<<B * TILES_PER_B * DSPLIT, NWARP * 32>>>(x, mask, out);
}

// round 11
// speedup vs baseline: 1.1032x; 1.1032x over previous
#include <cuda_runtime.h>
#include <cstdint>

// TemporalPyramidPooling: overlapping masked window means at w=4/8/16, stride w/2.
// Hierarchical non-overlapping pair sums, computed in packed f32x2 (Blackwell FFMA2-class
// ops, PTX-only: add.rn.f32x2 / mul.rn.f32x2). Data loaded/stored as v2.b64 so values
// live as f32x2 pairs end-to-end (no pack/unpack MOVs).
// R11 = R9 shape (1-warp CTAs, GPB=4, DSPLIT=4, evict_last x loads, streaming stores)
//       + packed-fp32 math (~halves fp instruction count per group).
//
//   x    [B=8, T=4096, D=512] f32
//   mask [B, T]  (bool; stored as 1-byte or int32 0/1 -- detected at runtime)
// Outputs concatenated f32:
//   vis4 [B,2047,D], vis8 [B,1023,D], vis16 [B,511,D],
//   msk4 [B,2047],   msk8 [B,1023],   msk16 [B,511]

namespace {
constexpr int B   = 8;
constexpr int T   = 4096;
constexpr int D   = 512;
constexpr int D4  = D / 4;                  // 128 float4 lanes
constexpr int S4  = 2047;
constexpr int S8  = 1023;
constexpr int S16 = 511;
constexpr int NGROUPS = T / 8;              // 512 pair8 groups per batch
constexpr int GPB = 4;                      // groups per block (tile = 32 t)
constexpr int BLOCKS_PER_B = NGROUPS / GPB; // 128
constexpr int DSPLIT = 4;                   // CTAs per (b, gtile) along D
constexpr int BLK = D4 / DSPLIT;            // 32 threads = 1 warp
}

// 1/max(count,1e-6) for counts 0..16 (count==0 -> sum==0, product 0 matches ref)
__constant__ float c_inv[17] = {
    1e6f, 1.0f, 0.5f, 1.0f/3.0f, 0.25f, 0.2f, 1.0f/6.0f, 1.0f/7.0f,
    0.125f, 1.0f/9.0f, 0.1f, 1.0f/11.0f, 1.0f/12.0f, 1.0f/13.0f,
    1.0f/14.0f, 1.0f/15.0f, 0.0625f
};

// ---- packed f32x2 helpers (4 floats = 2 x u64) ----
struct P2 { uint64_t a, b; };

__device__ __forceinline__ uint64_t addx2(uint64_t x, uint64_t y) {
    uint64_t r; asm("add.rn.f32x2 %0, %1, %2;" : "=l"(r) : "l"(x), "l"(y)); return r;
}
__device__ __forceinline__ uint64_t mulx2(uint64_t x, uint64_t y) {
    uint64_t r; asm("mul.rn.f32x2 %0, %1, %2;" : "=l"(r) : "l"(x), "l"(y)); return r;
}
__device__ __forceinline__ uint64_t bcast2(float s) {
    uint64_t r; asm("mov.b64 %0, {%1, %1};" : "=l"(r) : "f"(s)); return r;
}
__device__ __forceinline__ P2 p2zero() { P2 r; r.a = 0ull; r.b = 0ull; return r; }
__device__ __forceinline__ P2 p2add(P2 x, P2 y) { P2 r; r.a = addx2(x.a, y.a); r.b = addx2(x.b, y.b); return r; }
__device__ __forceinline__ P2 p2scale(P2 x, float s) {
    const uint64_t s2 = bcast2(s);
    P2 r; r.a = mulx2(x.a, s2); r.b = mulx2(x.b, s2); return r;
}

__device__ __forceinline__ uint64_t make_evict_last_policy() {
    uint64_t pol;
    asm("createpolicy.fractional.L2::evict_last.b64 %0, 1.0;" : "=l"(pol));
    return pol;
}
// 16B read-only load with L2 evict-last, directly into two f32x2 regs.
__device__ __forceinline__ P2 ldg_el(const void* p, uint64_t pol) {
    P2 r;
    asm("ld.global.nc.L2::cache_hint.v2.b64 {%0,%1}, [%2], %3;"
        : "=l"(r.a), "=l"(r.b) : "l"(p), "l"(pol));
    return r;
}
// 16B streaming (evict-first) store from two f32x2 regs.
__device__ __forceinline__ void stcs16(void* p, P2 v) {
    asm("st.global.cs.v2.b64 [%0], {%1,%2};" :: "l"(p), "l"(v.a), "l"(v.b) : "memory");
}

struct GroupSums {
    P2 c0, c1, c2, c3;   // pair2 sums
    P2 d0, d1;           // pair4 sums
    P2 e;                // pair8 sum
    int n0, n1, n2, n3, m0, m1, q;
};

// Load + mask + hierarchical-sum one pair8 group.
__device__ __forceinline__ GroupSums load_group(
    const char* __restrict__ xb, const void* __restrict__ mask_raw,
    bool mask_is_byte, int b, int g, uint64_t pol)
{
    const int t0 = g * 8;
    int mi[8];
    if (mask_is_byte) {
        const uint8_t* mb = (const uint8_t*)mask_raw + (size_t)b * T + t0;
        const uint64_t mw = *reinterpret_cast<const uint64_t*>(mb);
        #pragma unroll
        for (int i = 0; i < 8; ++i) mi[i] = (int)((mw >> (8 * i)) & 1u);
    } else {
        const int4* mw = reinterpret_cast<const int4*>(
            (const int*)mask_raw + (size_t)b * T + t0);
        int4 a = mw[0], c = mw[1];
        mi[0] = (a.x != 0); mi[1] = (a.y != 0); mi[2] = (a.z != 0); mi[3] = (a.w != 0);
        mi[4] = (c.x != 0); mi[5] = (c.y != 0); mi[6] = (c.z != 0); mi[7] = (c.w != 0);
    }

    P2 v[8];
    #pragma unroll
    for (int i = 0; i < 8; ++i)
        v[i] = ldg_el(xb + (size_t)(t0 + i) * (D4 * 16), pol);
    #pragma unroll
    for (int i = 0; i < 8; ++i) {
        v[i].a = mi[i] ? v[i].a : 0ull;   // zero-select == x * mask_f (ref semantics)
        v[i].b = mi[i] ? v[i].b : 0ull;
    }

    GroupSums s;
    s.c0 = p2add(v[0], v[1]); s.c1 = p2add(v[2], v[3]);
    s.c2 = p2add(v[4], v[5]); s.c3 = p2add(v[6], v[7]);
    s.n0 = mi[0] + mi[1]; s.n1 = mi[2] + mi[3];
    s.n2 = mi[4] + mi[5]; s.n3 = mi[6] + mi[7];
    s.d0 = p2add(s.c0, s.c1); s.d1 = p2add(s.c2, s.c3);
    s.m0 = s.n0 + s.n1; s.m1 = s.n2 + s.n3;
    s.e  = p2add(s.d0, s.d1);
    s.q  = s.m0 + s.m1;
    return s;
}

__global__ void __launch_bounds__(BLK)
tpp_kernel(const char* __restrict__ x,
           const void* __restrict__ mask_raw,
           float* __restrict__ out)
{
    const int blk   = blockIdx.x;               // 0..4095
    const int dpart = blk % DSPLIT;             // adjacent CTAs share the tile
    const int tile  = blk / DSPLIT;             // 0..1023
    const int b     = tile / BLOCKS_PER_B;
    const int g0    = (tile % BLOCKS_PER_B) * GPB;
    const int d4    = dpart * BLK + threadIdx.x;   // 0..127

    const uint64_t pol = make_evict_last_policy();

    // ---- mask storage-layout detection (byte vs int32), warp-uniform ----
    unsigned w = ((const unsigned*)mask_raw)[threadIdx.x];
    const bool mask_is_byte = __any_sync(0xffffffffu, w > 1u);

    const char* xb = x + ((size_t)b * T * D4 + d4) * 16;

    char* const vis4  = (char*)out;
    char* const vis8  = vis4  + (size_t)B * S4  * D4 * 16;
    char* const vis16 = vis8  + (size_t)B * S8  * D4 * 16;
    float* const msk4 = out + (size_t)B * (S4 + S8 + S16) * D;
    float* const msk8 = msk4 + B * S4;
    float* const msk16= msk8 + B * S8;

    const bool writeMsk = (threadIdx.x == 0) && (dpart == 0);

    P2  prev_c3 = p2zero(), prev_d1 = p2zero(), prev_e = p2zero();
    int prev_n3 = 0,        prev_m1 = 0,        prev_q = 0;

    #pragma unroll
    for (int k = 0; k < GPB; ++k) {
        const int g = g0 + k;
        const GroupSums s = load_group(xb, mask_raw, mask_is_byte, b, g, pol);

        if (k > 0) {
            {   // win4 at 4g-1 (crosses group boundary)
                const int si = 4 * g - 1;
                const int cnt = prev_n3 + s.n0;
                stcs16(vis4 + ((size_t)(b * S4 + si) * D4 + d4) * 16,
                       p2scale(p2add(prev_c3, s.c0), c_inv[cnt]));
                if (writeMsk) __stcs(&msk4[b * S4 + si], (cnt > 0) ? 1.0f : 0.0f);
            }
            {   // win8 at 2g-1
                const int h = 2 * g - 1;
                const int cnt = prev_m1 + s.m0;
                stcs16(vis8 + ((size_t)(b * S8 + h) * D4 + d4) * 16,
                       p2scale(p2add(prev_d1, s.d0), c_inv[cnt]));
                if (writeMsk) __stcs(&msk8[b * S8 + h], (cnt > 0) ? 1.0f : 0.0f);
            }
            {   // win16 at g-1
                const int cnt = prev_q + s.q;
                stcs16(vis16 + ((size_t)(b * S16 + (g - 1)) * D4 + d4) * 16,
                       p2scale(p2add(prev_e, s.e), c_inv[cnt]));
                if (writeMsk) __stcs(&msk16[b * S16 + (g - 1)], (cnt > 0) ? 1.0f : 0.0f);
            }
        }
        {   // in-tile outputs
            const int si = 4 * g;
            int cnt;
            cnt = s.n0 + s.n1;
            stcs16(vis4 + ((size_t)(b * S4 + si    ) * D4 + d4) * 16,
                   p2scale(p2add(s.c0, s.c1), c_inv[cnt]));
            if (writeMsk) __stcs(&msk4[b * S4 + si    ], (cnt > 0) ? 1.0f : 0.0f);
            cnt = s.n1 + s.n2;
            stcs16(vis4 + ((size_t)(b * S4 + si + 1) * D4 + d4) * 16,
                   p2scale(p2add(s.c1, s.c2), c_inv[cnt]));
            if (writeMsk) __stcs(&msk4[b * S4 + si + 1], (cnt > 0) ? 1.0f : 0.0f);
            cnt = s.n2 + s.n3;
            stcs16(vis4 + ((size_t)(b * S4 + si + 2) * D4 + d4) * 16,
                   p2scale(p2add(s.c2, s.c3), c_inv[cnt]));
            if (writeMsk) __stcs(&msk4[b * S4 + si + 2], (cnt > 0) ? 1.0f : 0.0f);

            const int h = 2 * g;
            cnt = s.m0 + s.m1;
            stcs16(vis8 + ((size_t)(b * S8 + h) * D4 + d4) * 16,
                   p2scale(p2add(s.d0, s.d1), c_inv[cnt]));
            if (writeMsk) __stcs(&msk8[b * S8 + h], (cnt > 0) ? 1.0f : 0.0f);
        }

        prev_c3 = s.c3; prev_d1 = s.d1; prev_e = s.e;
        prev_n3 = s.n3; prev_m1 = s.m1; prev_q = s.q;
    }

    // ---- halo epilogue: boundary windows into group gEnd (owned by this block) ----
    const int gEnd = g0 + GPB;
    if (gEnd < NGROUPS) {
        const GroupSums s = load_group(xb, mask_raw, mask_is_byte, b, gEnd, pol);
        {   // win4 at 4*gEnd-1
            const int si = 4 * gEnd - 1;
            const int cnt = prev_n3 + s.n0;
            stcs16(vis4 + ((size_t)(b * S4 + si) * D4 + d4) * 16,
                   p2scale(p2add(prev_c3, s.c0), c_inv[cnt]));
            if (writeMsk) __stcs(&msk4[b * S4 + si], (cnt > 0) ? 1.0f : 0.0f);
        }
        {   // win8 at 2*gEnd-1
            const int h = 2 * gEnd - 1;
            const int cnt = prev_m1 + s.m0;
            stcs16(vis8 + ((size_t)(b * S8 + h) * D4 + d4) * 16,
                   p2scale(p2add(prev_d1, s.d0), c_inv[cnt]));
            if (writeMsk) __stcs(&msk8[b * S8 + h], (cnt > 0) ? 1.0f : 0.0f);
        }
        {   // win16 at gEnd-1
            const int cnt = prev_q + s.q;
            stcs16(vis16 + ((size_t)(b * S16 + (gEnd - 1)) * D4 + d4) * 16,
                   p2scale(p2add(prev_e, s.e), c_inv[cnt]));
            if (writeMsk) __stcs(&msk16[b * S16 + (gEnd - 1)], (cnt > 0) ? 1.0f : 0.0f);
        }
    }
}

extern "C" void kernel_launch(void* const* d_in, const int* in_sizes, int n_in,
                              void* d_out, int out_size)
{
    const char* x    = (const char*)d_in[0];
    const void* mask = (const void*)d_in[1];
    float*      out  = (float*)d_out;

    tpp_kernel<<<B * BLOCKS_PER_B * DSPLIT, BLK>>>(x, mask, out);
}